// round 2
// baseline (speedup 1.0000x reference)
#include <cuda_runtime.h>
#include <cuda_bf16.h>
#include <math.h>

// Problem constants
#define TT 1024
#define BB 64
#define DD 512
#define HH 512
#define GG 2048            // 4*H
#define EPSV 1e-5f
#define OUT_HC_OFF (TT * BB * HH)
#define NBLK 128
#define THR 256

// Scratch (device globals — no runtime allocation allowed)
__device__ float g_xw[(size_t)TT * BB * GG];   // 512 MB: x @ W_x + bias
__device__ float g_part[4 * BB * GG];          // K-split partials of h @ W_h
__device__ float g_h[BB * HH];
__device__ float g_c0[BB * HH];

// grid barrier state (reset every launch by init kernel)
__device__ unsigned g_count;
__device__ volatile unsigned g_release;

// ---------------------------------------------------------------------------
__global__ void init_kernel(const float* __restrict__ h0,
                            const float* __restrict__ c0) {
    int i = blockIdx.x * blockDim.x + threadIdx.x;
    if (i == 0) { g_count = 0; g_release = 0; }
    if (i < BB * HH) {
        g_h[i] = h0[i];
        g_c0[i] = c0[i];
    }
}

// ---------------------------------------------------------------------------
// Big GEMM: XW[t*B+b][j] = sum_d x[t][b][d] * W[d][j] + bias[j]
// M = T*B = 65536, N = 2048, K = 512.  128x128 tile, BK=8, 256 thr, 8x8 micro.
// ---------------------------------------------------------------------------
__global__ void sgemm_x_kernel(const float* __restrict__ X,
                               const float* __restrict__ W,
                               const float* __restrict__ bias) {
    __shared__ float As[8][128];
    __shared__ float Bs[8][128];

    const int bn = blockIdx.x * 128;
    const int bm = blockIdx.y * 128;
    const int tid = threadIdx.x;
    const int tx = tid & 15;
    const int ty = tid >> 4;

    float acc[8][8];
#pragma unroll
    for (int i = 0; i < 8; i++)
#pragma unroll
        for (int j = 0; j < 8; j++) acc[i][j] = 0.f;

    const int a_row = tid >> 1;
    const int a_col = (tid & 1) * 4;
    const int b_row = tid >> 5;
    const int b_col = (tid & 31) * 4;

    const float* Aptr = X + (size_t)(bm + a_row) * DD + a_col;
    const float* Bptr = W + (size_t)b_row * GG + bn + b_col;

    for (int kt = 0; kt < DD; kt += 8) {
        float4 av = *(const float4*)(Aptr + kt);
        As[a_col + 0][a_row] = av.x;
        As[a_col + 1][a_row] = av.y;
        As[a_col + 2][a_row] = av.z;
        As[a_col + 3][a_row] = av.w;
        float4 bv = *(const float4*)(Bptr + (size_t)kt * GG);
        *(float4*)&Bs[b_row][b_col] = bv;
        __syncthreads();

#pragma unroll
        for (int k = 0; k < 8; k++) {
            float a[8], b[8];
            *(float4*)(a)     = *(const float4*)&As[k][ty * 8];
            *(float4*)(a + 4) = *(const float4*)&As[k][ty * 8 + 4];
            *(float4*)(b)     = *(const float4*)&Bs[k][tx * 8];
            *(float4*)(b + 4) = *(const float4*)&Bs[k][tx * 8 + 4];
#pragma unroll
            for (int i = 0; i < 8; i++)
#pragma unroll
                for (int j = 0; j < 8; j++) acc[i][j] = fmaf(a[i], b[j], acc[i][j]);
        }
        __syncthreads();
    }

#pragma unroll
    for (int i = 0; i < 8; i++) {
        size_t row = (size_t)(bm + ty * 8 + i) * GG + bn + tx * 8;
#pragma unroll
        for (int j = 0; j < 8; j += 4) {
            float4 o;
            o.x = acc[i][j + 0] + bias[bn + tx * 8 + j + 0];
            o.y = acc[i][j + 1] + bias[bn + tx * 8 + j + 1];
            o.z = acc[i][j + 2] + bias[bn + tx * 8 + j + 2];
            o.w = acc[i][j + 3] + bias[bn + tx * 8 + j + 3];
            *(float4*)&g_xw[row + j] = o;
        }
    }
}

// ---------------------------------------------------------------------------
// Software grid barrier (monotonic index; all NBLK blocks co-resident).
// __threadfence() emits gpu-scope fence (CCTL.IVALL on sm_103a -> L1D inval).
// ---------------------------------------------------------------------------
__device__ __forceinline__ void grid_bar(unsigned barid) {
    __syncthreads();
    if (threadIdx.x == 0) {
        __threadfence();
        unsigned prev = atomicAdd(&g_count, 1u);
        if (prev == barid * NBLK - 1u) {
            __threadfence();
            g_release = barid;
        } else {
            while (g_release < barid) { }
            __threadfence();
        }
    }
    __syncthreads();
}

__device__ __forceinline__ float sigmoidf_(float x) {
    return 1.f / (1.f + expf(-x));
}

__device__ __forceinline__ void block_reduce2(float& s, float& sq, float* shm) {
    __syncthreads();
    int lane = threadIdx.x & 31;
    int wid = threadIdx.x >> 5;
#pragma unroll
    for (int o = 16; o > 0; o >>= 1) {
        s  += __shfl_down_sync(0xffffffffu, s, o);
        sq += __shfl_down_sync(0xffffffffu, sq, o);
    }
    if (lane == 0) { shm[wid] = s; shm[8 + wid] = sq; }
    __syncthreads();
    if (threadIdx.x == 0) {
        float a = 0.f, b = 0.f;
#pragma unroll
        for (int i = 0; i < 8; i++) { a += shm[i]; b += shm[8 + i]; }
        shm[0] = a; shm[8] = b;
    }
    __syncthreads();
    s = shm[0];
    sq = shm[8];
}

// ---------------------------------------------------------------------------
// Persistent recurrent kernel: 128 blocks x 256 threads, loops over all T.
// Phase 1 (all 128 blocks): partial GEMM  part[kc][b][j] (64x64 tile, K=128)
// Phase 2 (blocks 0..63):   LN(gates) + activations + c update + LN(c) + h
// Blocks 64..127 prefetch next step's xw into L2 during phase 2.
// ---------------------------------------------------------------------------
__global__ void lstm_persist(const float* __restrict__ W,
                             const float* __restrict__ gg,
                             const float* __restrict__ gb,
                             const float* __restrict__ cgam,
                             const float* __restrict__ cbet,
                             float* __restrict__ out) {
    __shared__ float smem[GG + 16];

    const float* Wh = W + (size_t)DD * GG;
    const int blk = blockIdx.x;
    const int tid = threadIdx.x;

    // phase-1 tile assignment
    const int jb = (blk & 31) * 64;
    const int kc = blk >> 5;              // 0..3
    const int k0 = kc * 128;
    const int tx = tid & 15;
    const int ty = tid >> 4;
    const int a_row = tid >> 2;           // 0..63
    const int a_col = (tid & 3) * 2;
    const int b_row = tid >> 5;           // 0..7
    const int b_col = (tid & 31) * 2;

    float* As = smem;          // [8][64]
    float* Bs = smem + 512;    // [8][64]

    // phase-2 persistent cell state in registers (blocks 0..63 only)
    float creg[2];
    if (blk < BB) {
#pragma unroll
        for (int u = 0; u < 2; u++)
            creg[u] = g_c0[blk * HH + tid + u * 256];
    }

    unsigned barid = 0;

    for (int t = 0; t < TT; t++) {
        // ---------------- phase 1: partial GEMM ----------------
        float acc[4][4];
#pragma unroll
        for (int i = 0; i < 4; i++)
#pragma unroll
            for (int j = 0; j < 4; j++) acc[i][j] = 0.f;

        for (int kt = 0; kt < 128; kt += 8) {
            float2 av = __ldcg((const float2*)&g_h[a_row * HH + k0 + kt + a_col]);
            As[(a_col + 0) * 64 + a_row] = av.x;
            As[(a_col + 1) * 64 + a_row] = av.y;
            float2 bv = *(const float2*)&Wh[(size_t)(k0 + kt + b_row) * GG + jb + b_col];
            Bs[b_row * 64 + b_col + 0] = bv.x;
            Bs[b_row * 64 + b_col + 1] = bv.y;
            __syncthreads();

#pragma unroll
            for (int k = 0; k < 8; k++) {
                float a[4], b[4];
                *(float4*)a = *(const float4*)&As[k * 64 + ty * 4];
                *(float4*)b = *(const float4*)&Bs[k * 64 + tx * 4];
#pragma unroll
                for (int i = 0; i < 4; i++)
#pragma unroll
                    for (int j = 0; j < 4; j++)
                        acc[i][j] = fmaf(a[i], b[j], acc[i][j]);
            }
            __syncthreads();
        }
#pragma unroll
        for (int i = 0; i < 4; i++) {
            int b = ty * 4 + i;
            size_t base = ((size_t)kc * BB + b) * GG + jb + tx * 4;
            *(float4*)&g_part[base] = *(float4*)acc[i];
        }

        grid_bar(++barid);

        // ---------------- phase 2: LN + activations ----------------
        if (blk < BB) {
            const int b = blk;
            const float* xw = g_xw + ((size_t)t * BB + b) * GG;
            float* shm = smem + GG;

            float v[8];
            float s = 0.f, sq = 0.f;
#pragma unroll
            for (int u = 0; u < 8; u++) {
                int j = tid + u * 256;
                float val = __ldcg(&xw[j])
                          + __ldcg(&g_part[0 * BB * GG + b * GG + j])
                          + __ldcg(&g_part[1 * BB * GG + b * GG + j])
                          + __ldcg(&g_part[2 * BB * GG + b * GG + j])
                          + __ldcg(&g_part[3 * BB * GG + b * GG + j]);
                v[u] = val;
                s += val;
                sq += val * val;
            }
            block_reduce2(s, sq, shm);
            float mean = s * (1.f / GG);
            float var = sq * (1.f / GG) - mean * mean;
            float rstd = rsqrtf(var + EPSV);

#pragma unroll
            for (int u = 0; u < 8; u++) {
                int j = tid + u * 256;
                smem[j] = (v[u] - mean) * rstd * gg[j] + gb[j];
            }
            __syncthreads();

            float cv[2], ov[2];
            float s2 = 0.f, sq2 = 0.f;
#pragma unroll
            for (int u = 0; u < 2; u++) {
                int j = tid + u * 256;
                float f = sigmoidf_(smem[j]);
                float ig = sigmoidf_(smem[HH + j]);
                float gt = tanhf(smem[2 * HH + j]);
                float o = sigmoidf_(smem[3 * HH + j]);
                float c = f * creg[u] + ig * gt;
                cv[u] = c;
                ov[u] = o;
                s2 += c;
                sq2 += c * c;
            }
            block_reduce2(s2, sq2, shm);
            float mean2 = s2 * (1.f / HH);
            float var2 = sq2 * (1.f / HH) - mean2 * mean2;
            float rstd2 = rsqrtf(var2 + EPSV);

#pragma unroll
            for (int u = 0; u < 2; u++) {
                int j = tid + u * 256;
                float cn = (cv[u] - mean2) * rstd2 * cgam[j] + cbet[j];
                float hn = ov[u] * tanhf(cn);
                creg[u] = cn;
                g_h[b * HH + j] = hn;
                out[((size_t)t * BB + b) * HH + j] = hn;
            }
        } else if (t + 1 < TT) {
            // blocks 64..127: prefetch next step's xw into L2
            int idx = (blk - BB) * THR + tid;   // 0..16383
            if (idx < 4096) {
                const float* p = g_xw + ((size_t)(t + 1) * BB) * GG + (size_t)idx * 32;
                asm volatile("prefetch.global.L2 [%0];" :: "l"(p));
            }
        }

        grid_bar(++barid);
    }

    // final h_last / c_last tail (each block owns its row's state)
    if (blk < BB) {
#pragma unroll
        for (int u = 0; u < 2; u++) {
            int j = tid + u * 256;
            out[OUT_HC_OFF + blk * HH + j] = __ldcg(&g_h[blk * HH + j]);
            out[OUT_HC_OFF + BB * HH + blk * HH + j] = creg[u];
        }
    }
}

// ---------------------------------------------------------------------------
extern "C" void kernel_launch(void* const* d_in, const int* in_sizes, int n_in,
                              void* d_out, int out_size) {
    const float* x    = (const float*)d_in[0];
    const float* h0   = (const float*)d_in[1];
    const float* c0   = (const float*)d_in[2];
    const float* w    = (const float*)d_in[3];
    const float* bias = (const float*)d_in[4];
    const float* gg   = (const float*)d_in[5];
    const float* gb   = (const float*)d_in[6];
    const float* cg   = (const float*)d_in[7];
    const float* cb   = (const float*)d_in[8];
    float* out = (float*)d_out;

    init_kernel<<<128, 256>>>(h0, c0);

    // X @ W_x + bias for all timesteps: M=65536, N=2048, K=512
    sgemm_x_kernel<<<dim3(GG / 128, (TT * BB) / 128), 256>>>(x, w, bias);

    // persistent recurrence: all 1024 steps in one launch
    lstm_persist<<<NBLK, THR>>>(w, gg, gb, cg, cb, out);
}

// round 3
// speedup vs baseline: 1.8953x; 1.8953x over previous
#include <cuda_runtime.h>
#include <cuda_bf16.h>
#include <math.h>

// Problem constants
#define TT 1024
#define BB 64
#define DD 512
#define HH 512
#define KK 1024            // D + H
#define GG 2048            // 4*H
#define EPSV 1e-5f
#define MM (TT * BB)       // 65536
#define OUT_HC_OFF (TT * BB * HH)
#define NBLK 128
#define THR 256

// Scratch (device globals — no runtime allocation allowed)
__device__ float g_xw[(size_t)MM * GG];                  // 512 MB
__device__ __nv_bfloat16 g_xhi[(size_t)MM * DD];         // 64 MB
__device__ __nv_bfloat16 g_xlo[(size_t)MM * DD];         // 64 MB
__device__ __nv_bfloat16 g_whi[(size_t)GG * KK];         // W^T [n][k], 4 MB
__device__ __nv_bfloat16 g_wlo[(size_t)GG * KK];
__device__ __nv_bfloat16 g_hhi[BB * HH];
__device__ __nv_bfloat16 g_hlo[BB * HH];
__device__ float g_h[BB * HH];
__device__ float g_c0[BB * HH];
__device__ float g_part[4 * BB * GG];
__device__ unsigned g_count;
__device__ volatile unsigned g_release;

__device__ __forceinline__ void split2(float v, __nv_bfloat16& hi, __nv_bfloat16& lo) {
    hi = __float2bfloat16(v);
    lo = __float2bfloat16(v - __bfloat162float(hi));
}

// mma.sync m16n8k16 bf16 -> f32
__device__ __forceinline__ void mma_bf16(float* d, const unsigned* a, const unsigned* b) {
    asm volatile(
        "mma.sync.aligned.m16n8k16.row.col.f32.bf16.bf16.f32 "
        "{%0,%1,%2,%3}, {%4,%5,%6,%7}, {%8,%9}, {%0,%1,%2,%3};\n"
        : "+f"(d[0]), "+f"(d[1]), "+f"(d[2]), "+f"(d[3])
        : "r"(a[0]), "r"(a[1]), "r"(a[2]), "r"(a[3]), "r"(b[0]), "r"(b[1]));
}

// ---------------------------------------------------------------------------
__global__ void init_kernel(const float* __restrict__ h0,
                            const float* __restrict__ c0) {
    int i = blockIdx.x * blockDim.x + threadIdx.x;
    if (i == 0) { g_count = 0; g_release = 0; }
    if (i < BB * HH) {
        split2(h0[i], g_hhi[i], g_hlo[i]);
        g_h[i] = h0[i];
        g_c0[i] = c0[i];
    }
}

// split + transpose W [k][n] fp32 -> W^T [n][k] bf16 hi/lo
__global__ void split_w_kernel(const float* __restrict__ w) {
    int idx = blockIdx.x * blockDim.x + threadIdx.x;
    if (idx < KK * GG) {
        int k = idx / GG;
        int n = idx % GG;
        __nv_bfloat16 hi, lo;
        split2(w[idx], hi, lo);
        g_whi[(size_t)n * KK + k] = hi;
        g_wlo[(size_t)n * KK + k] = lo;
    }
}

// split x (same layout, k contiguous)
__global__ void split_x_kernel(const float* __restrict__ x) {
    size_t idx = (size_t)blockIdx.x * blockDim.x + threadIdx.x;
    if (idx < (size_t)MM * DD) {
        split2(x[idx], g_xhi[idx], g_xlo[idx]);
    }
}

// ---------------------------------------------------------------------------
// XW = X @ Wx + bias via bf16-split HMMA.  M=65536, N=2048, K=512.
// Block 128x128, BK=32, 256 thr = 8 warps (2m x 4n), warp tile 64x32.
// ---------------------------------------------------------------------------
__global__ void __launch_bounds__(256, 1) gemm_x_kernel(const float* __restrict__ bias) {
    __shared__ __nv_bfloat16 Ah[128][40], Al[128][40], Bh[128][40], Bl[128][40];

    const int bn = blockIdx.x * 128;
    const int bm = blockIdx.y * 128;
    const int tid = threadIdx.x;
    const int wid = tid >> 5, lane = tid & 31;
    const int wm = wid & 1, wn = wid >> 1;
    const int lr = lane >> 2, lc = lane & 3;

    float acc[4][4][4];
#pragma unroll
    for (int i = 0; i < 4; i++)
#pragma unroll
        for (int j = 0; j < 4; j++)
#pragma unroll
            for (int q = 0; q < 4; q++) acc[i][j][q] = 0.f;

    const int ldr = tid >> 1;           // 0..127
    const int ldc = (tid & 1) * 16;     // 0 or 16

    for (int k0 = 0; k0 < DD; k0 += 32) {
        const uint4* s;
        s = (const uint4*)&g_xhi[(size_t)(bm + ldr) * DD + k0 + ldc];
        *(uint4*)&Ah[ldr][ldc] = s[0];  *(uint4*)&Ah[ldr][ldc + 8] = s[1];
        s = (const uint4*)&g_xlo[(size_t)(bm + ldr) * DD + k0 + ldc];
        *(uint4*)&Al[ldr][ldc] = s[0];  *(uint4*)&Al[ldr][ldc + 8] = s[1];
        s = (const uint4*)&g_whi[(size_t)(bn + ldr) * KK + k0 + ldc];
        *(uint4*)&Bh[ldr][ldc] = s[0];  *(uint4*)&Bh[ldr][ldc + 8] = s[1];
        s = (const uint4*)&g_wlo[(size_t)(bn + ldr) * KK + k0 + ldc];
        *(uint4*)&Bl[ldr][ldc] = s[0];  *(uint4*)&Bl[ldr][ldc + 8] = s[1];
        __syncthreads();

#pragma unroll
        for (int ks = 0; ks < 32; ks += 16) {
            unsigned ahi[4][4], alo[4][4], bhi[4][2], blo[4][2];
#pragma unroll
            for (int im = 0; im < 4; im++) {
                int r = wm * 64 + im * 16 + lr;
                ahi[im][0] = *(const unsigned*)&Ah[r][ks + lc * 2];
                ahi[im][1] = *(const unsigned*)&Ah[r + 8][ks + lc * 2];
                ahi[im][2] = *(const unsigned*)&Ah[r][ks + 8 + lc * 2];
                ahi[im][3] = *(const unsigned*)&Ah[r + 8][ks + 8 + lc * 2];
                alo[im][0] = *(const unsigned*)&Al[r][ks + lc * 2];
                alo[im][1] = *(const unsigned*)&Al[r + 8][ks + lc * 2];
                alo[im][2] = *(const unsigned*)&Al[r][ks + 8 + lc * 2];
                alo[im][3] = *(const unsigned*)&Al[r + 8][ks + 8 + lc * 2];
            }
#pragma unroll
            for (int in = 0; in < 4; in++) {
                int n = wn * 32 + in * 8 + lr;
                bhi[in][0] = *(const unsigned*)&Bh[n][ks + lc * 2];
                bhi[in][1] = *(const unsigned*)&Bh[n][ks + 8 + lc * 2];
                blo[in][0] = *(const unsigned*)&Bl[n][ks + lc * 2];
                blo[in][1] = *(const unsigned*)&Bl[n][ks + 8 + lc * 2];
            }
#pragma unroll
            for (int im = 0; im < 4; im++)
#pragma unroll
                for (int in = 0; in < 4; in++) {
                    mma_bf16(acc[im][in], ahi[im], bhi[in]);
                    mma_bf16(acc[im][in], alo[im], bhi[in]);
                    mma_bf16(acc[im][in], ahi[im], blo[in]);
                }
        }
        __syncthreads();
    }

#pragma unroll
    for (int im = 0; im < 4; im++)
#pragma unroll
        for (int in = 0; in < 4; in++) {
            int row = bm + wm * 64 + im * 16 + lr;
            int col = bn + wn * 32 + in * 8 + lc * 2;
            float b0 = bias[col], b1 = bias[col + 1];
            float2 v;
            v.x = acc[im][in][0] + b0; v.y = acc[im][in][1] + b1;
            *(float2*)&g_xw[(size_t)row * GG + col] = v;
            v.x = acc[im][in][2] + b0; v.y = acc[im][in][3] + b1;
            *(float2*)&g_xw[(size_t)(row + 8) * GG + col] = v;
        }
}

// ---------------------------------------------------------------------------
__device__ __forceinline__ void grid_bar(unsigned barid) {
    __syncthreads();
    if (threadIdx.x == 0) {
        __threadfence();
        unsigned prev = atomicAdd(&g_count, 1u);
        if (prev == barid * NBLK - 1u) {
            __threadfence();
            g_release = barid;
        } else {
            while (g_release < barid) { }
            __threadfence();
        }
    }
    __syncthreads();
}

__device__ __forceinline__ float sigmoidf_(float x) {
    return 1.f / (1.f + expf(-x));
}

__device__ __forceinline__ void block_reduce2(float& s, float& sq, float* shm) {
    __syncthreads();
    int lane = threadIdx.x & 31;
    int wid = threadIdx.x >> 5;
#pragma unroll
    for (int o = 16; o > 0; o >>= 1) {
        s  += __shfl_down_sync(0xffffffffu, s, o);
        sq += __shfl_down_sync(0xffffffffu, sq, o);
    }
    if (lane == 0) { shm[wid] = s; shm[8 + wid] = sq; }
    __syncthreads();
    if (threadIdx.x == 0) {
        float a = 0.f, b = 0.f;
#pragma unroll
        for (int i = 0; i < 8; i++) { a += shm[i]; b += shm[8 + i]; }
        shm[0] = a; shm[8] = b;
    }
    __syncthreads();
    s = shm[0];
    sq = shm[8];
}

// ---------------------------------------------------------------------------
// Persistent recurrence. 128 blocks x 256 thr.
// Phase 1 (all): bf16-split HMMA partial GEMM, W tile smem-resident all steps.
//   block = (jb = (blk&31)*64 n-cols, kc = blk>>5 k-chunk of 128)
// Phase 2 (blk<64): LN(gates)+act+LN(c), write h (fp32 + bf16 hi/lo).
// ---------------------------------------------------------------------------
__global__ void __launch_bounds__(256, 1) lstm_persist(
        const float* __restrict__ gg, const float* __restrict__ gb,
        const float* __restrict__ cgam, const float* __restrict__ cbet,
        float* __restrict__ out) {
    extern __shared__ unsigned char sm8[];
    __nv_bfloat16* Whs = (__nv_bfloat16*)sm8;        // [64][136]
    __nv_bfloat16* Wls = Whs + 64 * 136;
    __nv_bfloat16* Ahs = Wls + 64 * 136;             // [64][136]
    __nv_bfloat16* Als = Ahs + 64 * 136;
    float* gates = (float*)(Als + 64 * 136);         // [2048]
    float* red = gates + GG;                         // [16]

    const int blk = blockIdx.x;
    const int tid = threadIdx.x;
    const int wid = tid >> 5, lane = tid & 31;
    const int wm = wid & 1, wn = wid >> 1;
    const int lr = lane >> 2, lc = lane & 3;

    const int jb = (blk & 31) * 64;
    const int kc = blk >> 5;
    const int k0 = kc * 128;

    // one-time: load resident W^T tile [64 n][128 k] hi/lo
    {
        int r = tid >> 2;                 // 0..63
        int seg = (tid & 3) * 32;         // 0,32,64,96
        const uint4* s = (const uint4*)&g_whi[(size_t)(jb + r) * KK + DD + k0 + seg];
        uint4* d = (uint4*)&Whs[r * 136 + seg];
        d[0] = s[0]; d[1] = s[1]; d[2] = s[2]; d[3] = s[3];
        s = (const uint4*)&g_wlo[(size_t)(jb + r) * KK + DD + k0 + seg];
        d = (uint4*)&Wls[r * 136 + seg];
        d[0] = s[0]; d[1] = s[1]; d[2] = s[2]; d[3] = s[3];
    }

    float creg[2];
    if (blk < BB) {
#pragma unroll
        for (int u = 0; u < 2; u++)
            creg[u] = g_c0[blk * HH + tid + u * 256];
    }

    unsigned barid = 0;

    for (int t = 0; t < TT; t++) {
        // ----- phase 1: load h tile, HMMA -----
        {
            int r = tid >> 2;
            int seg = (tid & 3) * 32;
            uint4* d = (uint4*)&Ahs[r * 136 + seg];
            const uint4* s = (const uint4*)&g_hhi[r * HH + k0 + seg];
            d[0] = __ldcg(s + 0); d[1] = __ldcg(s + 1);
            d[2] = __ldcg(s + 2); d[3] = __ldcg(s + 3);
            d = (uint4*)&Als[r * 136 + seg];
            s = (const uint4*)&g_hlo[r * HH + k0 + seg];
            d[0] = __ldcg(s + 0); d[1] = __ldcg(s + 1);
            d[2] = __ldcg(s + 2); d[3] = __ldcg(s + 3);
        }
        __syncthreads();

        float acc[2][2][4];
#pragma unroll
        for (int i = 0; i < 2; i++)
#pragma unroll
            for (int j = 0; j < 2; j++)
#pragma unroll
                for (int q = 0; q < 4; q++) acc[i][j][q] = 0.f;

#pragma unroll
        for (int ks = 0; ks < 128; ks += 16) {
            unsigned ahi[2][4], alo[2][4], bhi[2][2], blo[2][2];
#pragma unroll
            for (int im = 0; im < 2; im++) {
                int r = wm * 32 + im * 16 + lr;
                ahi[im][0] = *(const unsigned*)&Ahs[r * 136 + ks + lc * 2];
                ahi[im][1] = *(const unsigned*)&Ahs[(r + 8) * 136 + ks + lc * 2];
                ahi[im][2] = *(const unsigned*)&Ahs[r * 136 + ks + 8 + lc * 2];
                ahi[im][3] = *(const unsigned*)&Ahs[(r + 8) * 136 + ks + 8 + lc * 2];
                alo[im][0] = *(const unsigned*)&Als[r * 136 + ks + lc * 2];
                alo[im][1] = *(const unsigned*)&Als[(r + 8) * 136 + ks + lc * 2];
                alo[im][2] = *(const unsigned*)&Als[r * 136 + ks + 8 + lc * 2];
                alo[im][3] = *(const unsigned*)&Als[(r + 8) * 136 + ks + 8 + lc * 2];
            }
#pragma unroll
            for (int in = 0; in < 2; in++) {
                int n = wn * 16 + in * 8 + lr;
                bhi[in][0] = *(const unsigned*)&Whs[n * 136 + ks + lc * 2];
                bhi[in][1] = *(const unsigned*)&Whs[n * 136 + ks + 8 + lc * 2];
                blo[in][0] = *(const unsigned*)&Wls[n * 136 + ks + lc * 2];
                blo[in][1] = *(const unsigned*)&Wls[n * 136 + ks + 8 + lc * 2];
            }
#pragma unroll
            for (int im = 0; im < 2; im++)
#pragma unroll
                for (int in = 0; in < 2; in++) {
                    mma_bf16(acc[im][in], ahi[im], bhi[in]);
                    mma_bf16(acc[im][in], alo[im], bhi[in]);
                    mma_bf16(acc[im][in], ahi[im], blo[in]);
                }
        }

#pragma unroll
        for (int im = 0; im < 2; im++)
#pragma unroll
            for (int in = 0; in < 2; in++) {
                int b = wm * 32 + im * 16 + lr;
                int j = jb + wn * 16 + in * 8 + lc * 2;
                float2 v;
                v.x = acc[im][in][0]; v.y = acc[im][in][1];
                *(float2*)&g_part[((size_t)kc * BB + b) * GG + j] = v;
                v.x = acc[im][in][2]; v.y = acc[im][in][3];
                *(float2*)&g_part[((size_t)kc * BB + b + 8) * GG + j] = v;
            }

        grid_bar(++barid);

        // ----- phase 2 -----
        if (blk < BB) {
            const int b = blk;
            const float* xw = g_xw + ((size_t)t * BB + b) * GG;

            float v[8];
            float s = 0.f, sq = 0.f;
#pragma unroll
            for (int u = 0; u < 8; u++) {
                int j = tid + u * 256;
                float val = __ldcg(&xw[j])
                          + __ldcg(&g_part[0 * BB * GG + b * GG + j])
                          + __ldcg(&g_part[1 * BB * GG + b * GG + j])
                          + __ldcg(&g_part[2 * BB * GG + b * GG + j])
                          + __ldcg(&g_part[3 * BB * GG + b * GG + j]);
                v[u] = val;
                s += val;
                sq += val * val;
            }
            block_reduce2(s, sq, red);
            float mean = s * (1.f / GG);
            float var = sq * (1.f / GG) - mean * mean;
            float rstd = rsqrtf(var + EPSV);

#pragma unroll
            for (int u = 0; u < 8; u++) {
                int j = tid + u * 256;
                gates[j] = (v[u] - mean) * rstd * gg[j] + gb[j];
            }
            __syncthreads();

            float cv[2], ov[2];
            float s2 = 0.f, sq2 = 0.f;
#pragma unroll
            for (int u = 0; u < 2; u++) {
                int j = tid + u * 256;
                float f = sigmoidf_(gates[j]);
                float ig = sigmoidf_(gates[HH + j]);
                float gt = tanhf(gates[2 * HH + j]);
                float o = sigmoidf_(gates[3 * HH + j]);
                float c = f * creg[u] + ig * gt;
                cv[u] = c;
                ov[u] = o;
                s2 += c;
                sq2 += c * c;
            }
            block_reduce2(s2, sq2, red);
            float mean2 = s2 * (1.f / HH);
            float var2 = sq2 * (1.f / HH) - mean2 * mean2;
            float rstd2 = rsqrtf(var2 + EPSV);

#pragma unroll
            for (int u = 0; u < 2; u++) {
                int j = tid + u * 256;
                float cn = (cv[u] - mean2) * rstd2 * cgam[j] + cbet[j];
                float hn = ov[u] * tanhf(cn);
                creg[u] = cn;
                g_h[b * HH + j] = hn;
                __nv_bfloat16 hi, lo;
                split2(hn, hi, lo);
                g_hhi[b * HH + j] = hi;
                g_hlo[b * HH + j] = lo;
                out[((size_t)t * BB + b) * HH + j] = hn;
            }
        } else if (t + 1 < TT) {
            // blocks 64..127: prefetch next step's xw into L2
            int idx = (blk - BB) * THR + tid;
            if (idx < 4096) {
                const float* p = g_xw + ((size_t)(t + 1) * BB) * GG + (size_t)idx * 32;
                asm volatile("prefetch.global.L2 [%0];" :: "l"(p));
            }
        }

        grid_bar(++barid);
    }

    if (blk < BB) {
#pragma unroll
        for (int u = 0; u < 2; u++) {
            int j = tid + u * 256;
            out[OUT_HC_OFF + blk * HH + j] = __ldcg(&g_h[blk * HH + j]);
            out[OUT_HC_OFF + BB * HH + blk * HH + j] = creg[u];
        }
    }
}

// ---------------------------------------------------------------------------
extern "C" void kernel_launch(void* const* d_in, const int* in_sizes, int n_in,
                              void* d_out, int out_size) {
    const float* x    = (const float*)d_in[0];
    const float* h0   = (const float*)d_in[1];
    const float* c0   = (const float*)d_in[2];
    const float* w    = (const float*)d_in[3];
    const float* bias = (const float*)d_in[4];
    const float* gg   = (const float*)d_in[5];
    const float* gb   = (const float*)d_in[6];
    const float* cg   = (const float*)d_in[7];
    const float* cb   = (const float*)d_in[8];
    float* out = (float*)d_out;

    static bool attr_set = false;
    if (!attr_set) {
        cudaFuncSetAttribute(lstm_persist,
                             cudaFuncAttributeMaxDynamicSharedMemorySize, 77888);
        attr_set = true;
    }

    init_kernel<<<128, 256>>>(h0, c0);
    split_w_kernel<<<(KK * GG + 255) / 256, 256>>>(w);
    split_x_kernel<<<(int)(((size_t)MM * DD + 255) / 256), 256>>>(x);

    // XW = X @ Wx + bias : M=65536, N=2048, K=512
    gemm_x_kernel<<<dim3(GG / 128, MM / 128), 256>>>(bias);

    // persistent recurrence: all 1024 steps in one launch
    lstm_persist<<<NBLK, THR, 77888>>>(gg, gb, cg, cb, out);
}

// round 4
// speedup vs baseline: 1.8966x; 1.0007x over previous
#include <cuda_runtime.h>
#include <cuda_bf16.h>
#include <math.h>

// Problem constants
#define TT 1024
#define BB 64
#define DD 512
#define HH 512
#define KK 1024            // D + H
#define GG 2048            // 4*H
#define EPSV 1e-5f
#define MM (TT * BB)       // 65536
#define OUT_HC_OFF (TT * BB * HH)
#define NBLK 64
#define THR 512

// Scratch (device globals — no runtime allocation allowed)
__device__ float g_xw[(size_t)MM * GG];                  // 512 MB
__device__ __nv_bfloat16 g_xhi[(size_t)MM * DD];
__device__ __nv_bfloat16 g_xlo[(size_t)MM * DD];
__device__ __nv_bfloat16 g_whi[(size_t)GG * KK];         // W^T [n][k]
__device__ __nv_bfloat16 g_wlo[(size_t)GG * KK];
__device__ __nv_bfloat16 g_hhi[BB * HH];
__device__ __nv_bfloat16 g_hlo[BB * HH];
__device__ float g_c0[BB * HH];
__device__ float g_part[4 * BB * GG];
__device__ unsigned g_count;
__device__ unsigned g_release;

__device__ __forceinline__ void split2(float v, __nv_bfloat16& hi, __nv_bfloat16& lo) {
    hi = __float2bfloat16(v);
    lo = __float2bfloat16(v - __bfloat162float(hi));
}

__device__ __forceinline__ void mma_bf16(float* d, const unsigned* a, const unsigned* b) {
    asm volatile(
        "mma.sync.aligned.m16n8k16.row.col.f32.bf16.bf16.f32 "
        "{%0,%1,%2,%3}, {%4,%5,%6,%7}, {%8,%9}, {%0,%1,%2,%3};\n"
        : "+f"(d[0]), "+f"(d[1]), "+f"(d[2]), "+f"(d[3])
        : "r"(a[0]), "r"(a[1]), "r"(a[2]), "r"(a[3]), "r"(b[0]), "r"(b[1]));
}

__device__ __forceinline__ void ldsm_x4(unsigned* r, unsigned addr) {
    asm volatile("ldmatrix.sync.aligned.m8n8.x4.shared.b16 {%0,%1,%2,%3}, [%4];"
        : "=r"(r[0]), "=r"(r[1]), "=r"(r[2]), "=r"(r[3]) : "r"(addr));
}
__device__ __forceinline__ void ldsm_x2(unsigned* r, unsigned addr) {
    asm volatile("ldmatrix.sync.aligned.m8n8.x2.shared.b16 {%0,%1}, [%2];"
        : "=r"(r[0]), "=r"(r[1]) : "r"(addr));
}

// fence-free barrier primitives
__device__ __forceinline__ unsigned atom_add_release(unsigned* p, unsigned v) {
    unsigned old;
    asm volatile("atom.add.release.gpu.u32 %0, [%1], %2;"
                 : "=r"(old) : "l"(p), "r"(v) : "memory");
    return old;
}
__device__ __forceinline__ void st_release(unsigned* p, unsigned v) {
    asm volatile("st.release.gpu.u32 [%0], %1;" :: "l"(p), "r"(v) : "memory");
}
__device__ __forceinline__ unsigned ld_acquire(unsigned* p) {
    unsigned v;
    asm volatile("ld.acquire.gpu.u32 %0, [%1];" : "=r"(v) : "l"(p) : "memory");
    return v;
}

__device__ __forceinline__ void grid_bar(unsigned barid) {
    __syncthreads();
    if (threadIdx.x == 0) {
        unsigned prev = atom_add_release(&g_count, 1u);
        if (prev == barid * NBLK - 1u) {
            st_release(&g_release, barid);
        } else {
            while (ld_acquire(&g_release) < barid) { }
        }
    }
    __syncthreads();
}

__device__ __forceinline__ float fast_sig(float x) {
    return __fdividef(1.f, 1.f + __expf(-x));
}
__device__ __forceinline__ float fast_tanh(float x) {
    return __fdividef(2.f, 1.f + __expf(-2.f * x)) - 1.f;
}

// ---------------------------------------------------------------------------
__global__ void init_kernel(const float* __restrict__ h0,
                            const float* __restrict__ c0) {
    int i = blockIdx.x * blockDim.x + threadIdx.x;
    if (i == 0) { g_count = 0; g_release = 0; }
    if (i < BB * HH) {
        split2(h0[i], g_hhi[i], g_hlo[i]);
        g_c0[i] = c0[i];
    }
}

__global__ void split_w_kernel(const float* __restrict__ w) {
    int idx = blockIdx.x * blockDim.x + threadIdx.x;
    if (idx < KK * GG) {
        int k = idx / GG;
        int n = idx % GG;
        __nv_bfloat16 hi, lo;
        split2(w[idx], hi, lo);
        g_whi[(size_t)n * KK + k] = hi;
        g_wlo[(size_t)n * KK + k] = lo;
    }
}

__global__ void split_x_kernel(const float* __restrict__ x) {
    size_t idx = (size_t)blockIdx.x * blockDim.x + threadIdx.x;
    if (idx < (size_t)MM * DD) {
        split2(x[idx], g_xhi[idx], g_xlo[idx]);
    }
}

// ---------------------------------------------------------------------------
// XW = X @ Wx + bias via bf16-split HMMA.  M=65536, N=2048, K=512.
// Block 128x128, BK=32, 256 thr = 8 warps (2m x 4n), warp tile 64x32.
// ---------------------------------------------------------------------------
__global__ void __launch_bounds__(256, 1) gemm_x_kernel(const float* __restrict__ bias) {
    __shared__ __nv_bfloat16 Ah[128][40], Al[128][40], Bh[128][40], Bl[128][40];

    const int bn = blockIdx.x * 128;
    const int bm = blockIdx.y * 128;
    const int tid = threadIdx.x;
    const int wid = tid >> 5, lane = tid & 31;
    const int wm = wid & 1, wn = wid >> 1;
    const int lr = lane >> 2, lc = lane & 3;

    float acc[4][4][4];
#pragma unroll
    for (int i = 0; i < 4; i++)
#pragma unroll
        for (int j = 0; j < 4; j++)
#pragma unroll
            for (int q = 0; q < 4; q++) acc[i][j][q] = 0.f;

    const int ldr = tid >> 1;
    const int ldc = (tid & 1) * 16;

    for (int k0 = 0; k0 < DD; k0 += 32) {
        const uint4* s;
        s = (const uint4*)&g_xhi[(size_t)(bm + ldr) * DD + k0 + ldc];
        *(uint4*)&Ah[ldr][ldc] = s[0];  *(uint4*)&Ah[ldr][ldc + 8] = s[1];
        s = (const uint4*)&g_xlo[(size_t)(bm + ldr) * DD + k0 + ldc];
        *(uint4*)&Al[ldr][ldc] = s[0];  *(uint4*)&Al[ldr][ldc + 8] = s[1];
        s = (const uint4*)&g_whi[(size_t)(bn + ldr) * KK + k0 + ldc];
        *(uint4*)&Bh[ldr][ldc] = s[0];  *(uint4*)&Bh[ldr][ldc + 8] = s[1];
        s = (const uint4*)&g_wlo[(size_t)(bn + ldr) * KK + k0 + ldc];
        *(uint4*)&Bl[ldr][ldc] = s[0];  *(uint4*)&Bl[ldr][ldc + 8] = s[1];
        __syncthreads();

#pragma unroll
        for (int ks = 0; ks < 32; ks += 16) {
            unsigned ahi[4][4], alo[4][4], bhi[4][2], blo[4][2];
#pragma unroll
            for (int im = 0; im < 4; im++) {
                int r = wm * 64 + im * 16 + lr;
                ahi[im][0] = *(const unsigned*)&Ah[r][ks + lc * 2];
                ahi[im][1] = *(const unsigned*)&Ah[r + 8][ks + lc * 2];
                ahi[im][2] = *(const unsigned*)&Ah[r][ks + 8 + lc * 2];
                ahi[im][3] = *(const unsigned*)&Ah[r + 8][ks + 8 + lc * 2];
                alo[im][0] = *(const unsigned*)&Al[r][ks + lc * 2];
                alo[im][1] = *(const unsigned*)&Al[r + 8][ks + lc * 2];
                alo[im][2] = *(const unsigned*)&Al[r][ks + 8 + lc * 2];
                alo[im][3] = *(const unsigned*)&Al[r + 8][ks + 8 + lc * 2];
            }
#pragma unroll
            for (int in = 0; in < 4; in++) {
                int n = wn * 32 + in * 8 + lr;
                bhi[in][0] = *(const unsigned*)&Bh[n][ks + lc * 2];
                bhi[in][1] = *(const unsigned*)&Bh[n][ks + 8 + lc * 2];
                blo[in][0] = *(const unsigned*)&Bl[n][ks + lc * 2];
                blo[in][1] = *(const unsigned*)&Bl[n][ks + 8 + lc * 2];
            }
#pragma unroll
            for (int im = 0; im < 4; im++)
#pragma unroll
                for (int in = 0; in < 4; in++) {
                    mma_bf16(acc[im][in], ahi[im], bhi[in]);
                    mma_bf16(acc[im][in], alo[im], bhi[in]);
                    mma_bf16(acc[im][in], ahi[im], blo[in]);
                }
        }
        __syncthreads();
    }

#pragma unroll
    for (int im = 0; im < 4; im++)
#pragma unroll
        for (int in = 0; in < 4; in++) {
            int row = bm + wm * 64 + im * 16 + lr;
            int col = bn + wn * 32 + in * 8 + lc * 2;
            float b0 = bias[col], b1 = bias[col + 1];
            float2 v;
            v.x = acc[im][in][0] + b0; v.y = acc[im][in][1] + b1;
            *(float2*)&g_xw[(size_t)row * GG + col] = v;
            v.x = acc[im][in][2] + b0; v.y = acc[im][in][3] + b1;
            *(float2*)&g_xw[(size_t)(row + 8) * GG + col] = v;
        }
}

// ---------------------------------------------------------------------------
__device__ __forceinline__ void block_reduce2(float& s, float& sq, float* shm) {
    __syncthreads();
    int lane = threadIdx.x & 31;
    int wid = threadIdx.x >> 5;
#pragma unroll
    for (int o = 16; o > 0; o >>= 1) {
        s  += __shfl_down_sync(0xffffffffu, s, o);
        sq += __shfl_down_sync(0xffffffffu, sq, o);
    }
    if (lane == 0) { shm[wid] = s; shm[16 + wid] = sq; }
    __syncthreads();
    if (threadIdx.x == 0) {
        float a = 0.f, b = 0.f;
#pragma unroll
        for (int i = 0; i < 16; i++) { a += shm[i]; b += shm[16 + i]; }
        shm[0] = a; shm[16] = b;
    }
    __syncthreads();
    s = shm[0];
    sq = shm[16];
}

// ---------------------------------------------------------------------------
// Persistent recurrence: 64 blocks x 512 threads (16 warps: 2m x 8n).
// Block = (jb = (blk&15)*128 n-cols, kc = blk>>4 k-chunk of 128).
// Phase 1: h@Wh partials via HMMA + ldmatrix; W tile smem-resident all steps.
// Phase 2: every block owns batch row b=blk: LN + activations, no smem gates
//          (thread tid holds f,i,g,o of element tid directly).
// ---------------------------------------------------------------------------
__global__ void __launch_bounds__(THR, 1) lstm_persist(
        const float* __restrict__ gg, const float* __restrict__ gb,
        const float* __restrict__ cgam, const float* __restrict__ cbet,
        float* __restrict__ out) {
    extern __shared__ unsigned char sm8[];
    __nv_bfloat16* Whs = (__nv_bfloat16*)sm8;        // [128][136]
    __nv_bfloat16* Wls = Whs + 128 * 136;
    __nv_bfloat16* Ahs = Wls + 128 * 136;            // [64][136]
    __nv_bfloat16* Als = Ahs + 64 * 136;
    float* red = (float*)(Als + 64 * 136);           // [32]

    const int blk = blockIdx.x;
    const int tid = threadIdx.x;
    const int wid = tid >> 5, lane = tid & 31;
    const int wm = wid & 1, wn = wid >> 1;           // wm<2, wn<8
    const int lr = lane >> 2, lc = lane & 3;

    const int jb = (blk & 15) * 128;
    const int kc = blk >> 4;
    const int k0 = kc * 128;

    // one-time: resident W^T tile [128 n][128 k] hi/lo
    {
        int r = tid >> 2;                 // 0..127
        int seg = (tid & 3) * 32;
        const uint4* s = (const uint4*)&g_whi[(size_t)(jb + r) * KK + DD + k0 + seg];
        uint4* d = (uint4*)&Whs[r * 136 + seg];
        d[0] = s[0]; d[1] = s[1]; d[2] = s[2]; d[3] = s[3];
        s = (const uint4*)&g_wlo[(size_t)(jb + r) * KK + DD + k0 + seg];
        d = (uint4*)&Wls[r * 136 + seg];
        d[0] = s[0]; d[1] = s[1]; d[2] = s[2]; d[3] = s[3];
    }

    // ldmatrix lane addressing (constant per thread)
    const int a_g = lane >> 3;
    const int a_row_off = (a_g & 1) * 8 + (lane & 7);
    const int a_col_off = (a_g >> 1) * 8;
    const int b_row_off = lane & 7;
    const int b_col_off = ((lane >> 3) & 1) * 8;

    // phase-2 per-thread constants hoisted for all steps
    const int b = blk;                    // batch row owned in phase 2
    const float ggf = gg[tid],           gbf = gb[tid];
    const float ggi = gg[HH + tid],      gbi = gb[HH + tid];
    const float ggg = gg[2 * HH + tid],  gbg = gb[2 * HH + tid];
    const float ggo = gg[3 * HH + tid],  gbo = gb[3 * HH + tid];
    const float cga = cgam[tid], cbe = cbet[tid];

    float creg = g_c0[b * HH + tid];
    float hlast = 0.f;

    unsigned barid = 0;

    for (int t = 0; t < TT; t++) {
        // ----- phase 1: load h tile (64x128 hi/lo), HMMA -----
        {
            int r = tid >> 3;                 // 0..63
            int seg = (tid & 7) * 16;         // halfword offset
            const uint4* s = (const uint4*)&g_hhi[r * HH + k0 + seg];
            uint4* d = (uint4*)&Ahs[r * 136 + seg];
            d[0] = __ldcg(s + 0); d[1] = __ldcg(s + 1);
            s = (const uint4*)&g_hlo[r * HH + k0 + seg];
            d = (uint4*)&Als[r * 136 + seg];
            d[0] = __ldcg(s + 0); d[1] = __ldcg(s + 1);
        }
        __syncthreads();

        float acc[2][2][4];
#pragma unroll
        for (int i = 0; i < 2; i++)
#pragma unroll
            for (int j = 0; j < 2; j++)
#pragma unroll
                for (int q = 0; q < 4; q++) acc[i][j][q] = 0.f;

#pragma unroll
        for (int ks = 0; ks < 128; ks += 16) {
            unsigned ahi[2][4], alo[2][4], bhi[2][2], blo[2][2];
#pragma unroll
            for (int im = 0; im < 2; im++) {
                int r = wm * 32 + im * 16 + a_row_off;
                unsigned ad = (unsigned)__cvta_generic_to_shared(
                    &Ahs[r * 136 + ks + a_col_off]);
                ldsm_x4(ahi[im], ad);
                ad = (unsigned)__cvta_generic_to_shared(
                    &Als[r * 136 + ks + a_col_off]);
                ldsm_x4(alo[im], ad);
            }
#pragma unroll
            for (int in = 0; in < 2; in++) {
                int n = wn * 16 + in * 8 + b_row_off;
                unsigned ad = (unsigned)__cvta_generic_to_shared(
                    &Whs[n * 136 + ks + b_col_off]);
                ldsm_x2(bhi[in], ad);
                ad = (unsigned)__cvta_generic_to_shared(
                    &Wls[n * 136 + ks + b_col_off]);
                ldsm_x2(blo[in], ad);
            }
#pragma unroll
            for (int im = 0; im < 2; im++)
#pragma unroll
                for (int in = 0; in < 2; in++) {
                    mma_bf16(acc[im][in], ahi[im], bhi[in]);
                    mma_bf16(acc[im][in], alo[im], bhi[in]);
                    mma_bf16(acc[im][in], ahi[im], blo[in]);
                }
        }

#pragma unroll
        for (int im = 0; im < 2; im++)
#pragma unroll
            for (int in = 0; in < 2; in++) {
                int br = wm * 32 + im * 16 + lr;
                int j = jb + wn * 16 + in * 8 + lc * 2;
                float2 v;
                v.x = acc[im][in][0]; v.y = acc[im][in][1];
                *(float2*)&g_part[((size_t)kc * BB + br) * GG + j] = v;
                v.x = acc[im][in][2]; v.y = acc[im][in][3];
                *(float2*)&g_part[((size_t)kc * BB + br + 8) * GG + j] = v;
            }

        grid_bar(++barid);

        // ----- phase 2: row b = blk -----
        {
            const float* xw = g_xw + ((size_t)t * BB + b) * GG;

            float v[4];
            float s = 0.f, sq = 0.f;
#pragma unroll
            for (int u = 0; u < 4; u++) {
                int j = tid + u * THR;
                float val = __ldcg(&xw[j])
                          + __ldcg(&g_part[0 * BB * GG + b * GG + j])
                          + __ldcg(&g_part[1 * BB * GG + b * GG + j])
                          + __ldcg(&g_part[2 * BB * GG + b * GG + j])
                          + __ldcg(&g_part[3 * BB * GG + b * GG + j]);
                v[u] = val;
                s += val;
                sq += val * val;
            }
            block_reduce2(s, sq, red);
            float mean = s * (1.f / GG);
            float var = sq * (1.f / GG) - mean * mean;
            float rstd = rsqrtf(var + EPSV);

            float f  = fast_sig((v[0] - mean) * rstd * ggf + gbf);
            float ig = fast_sig((v[1] - mean) * rstd * ggi + gbi);
            float gt = fast_tanh((v[2] - mean) * rstd * ggg + gbg);
            float o  = fast_sig((v[3] - mean) * rstd * ggo + gbo);
            float c = f * creg + ig * gt;

            float s2 = c, sq2 = c * c;
            block_reduce2(s2, sq2, red);
            float mean2 = s2 * (1.f / HH);
            float var2 = sq2 * (1.f / HH) - mean2 * mean2;
            float rstd2 = rsqrtf(var2 + EPSV);

            float cn = (c - mean2) * rstd2 * cga + cbe;
            float hn = o * fast_tanh(cn);
            creg = cn;
            hlast = hn;

            __nv_bfloat16 hi, lo;
            split2(hn, hi, lo);
            g_hhi[b * HH + tid] = hi;
            g_hlo[b * HH + tid] = lo;
            out[((size_t)t * BB + b) * HH + tid] = hn;
        }

        grid_bar(++barid);
    }

    out[OUT_HC_OFF + b * HH + tid] = hlast;
    out[OUT_HC_OFF + BB * HH + b * HH + tid] = creg;
}

// ---------------------------------------------------------------------------
extern "C" void kernel_launch(void* const* d_in, const int* in_sizes, int n_in,
                              void* d_out, int out_size) {
    const float* x    = (const float*)d_in[0];
    const float* h0   = (const float*)d_in[1];
    const float* c0   = (const float*)d_in[2];
    const float* w    = (const float*)d_in[3];
    const float* bias = (const float*)d_in[4];
    const float* gg   = (const float*)d_in[5];
    const float* gb   = (const float*)d_in[6];
    const float* cg   = (const float*)d_in[7];
    const float* cb   = (const float*)d_in[8];
    float* out = (float*)d_out;

    static bool attr_set = false;
    if (!attr_set) {
        cudaFuncSetAttribute(lstm_persist,
                             cudaFuncAttributeMaxDynamicSharedMemorySize, 104832);
        attr_set = true;
    }

    init_kernel<<<128, 256>>>(h0, c0);
    split_w_kernel<<<(KK * GG + 255) / 256, 256>>>(w);
    split_x_kernel<<<(int)(((size_t)MM * DD + 255) / 256), 256>>>(x);

    // XW = X @ Wx + bias : M=65536, N=2048, K=512
    gemm_x_kernel<<<dim3(GG / 128, MM / 128), 256>>>(bias);

    // persistent recurrence: all 1024 steps in one launch
    lstm_persist<<<NBLK, THR, 104832>>>(gg, gb, cg, cb, out);
}